// round 2
// baseline (speedup 1.0000x reference)
#include <cuda_runtime.h>
#include <math.h>
#include <stdint.h>

#define B_     64
#define T_     1024
#define VOCAB_ 256
#define EMB_   128
#define HID_   512

// RNN partition: 4 batch groups x 32 column groups = 128 persistent CTAs
#define QG  4
#define PG  32
#define BQ  16     // batches per CTA
#define CJ  16     // hidden columns per CTA
#define NCTA (QG*PG)
#define RNN_THREADS 128
#define WPAD 516   // padded row stride in floats (512+4) for bank-conflict relief

// ---------------- device global scratch (no cudaMalloc allowed) ----------------
__device__ __align__(16) float g_E2[VOCAB_ * HID_];            // emb@w_ih0^T + b_ih0 + b_hh0
__device__ __align__(16) float g_h0[2][B_ * HID_];             // ping-pong layer0 state
__device__ __align__(16) float g_h1[2][B_ * HID_];             // ping-pong layer1 state
__device__ __align__(16) float g_hout[(size_t)B_ * T_ * HID_]; // all h1 outputs (128 MB)
__device__ unsigned g_bar_count[QG];
__device__ volatile unsigned g_bar_phase[QG];

// ---------------- prep: E2 table, zero initial state, reset barriers ----------------
__global__ void prep_kernel(const float* __restrict__ emb,
                            const float* __restrict__ w_ih0,
                            const float* __restrict__ b_ih0,
                            const float* __restrict__ b_hh0)
{
    int v = blockIdx.x;  // 0..255 vocab row
    __shared__ float se[EMB_];
    for (int k = threadIdx.x; k < EMB_; k += blockDim.x) se[k] = emb[v * EMB_ + k];
    __syncthreads();
    for (int j = threadIdx.x; j < HID_; j += blockDim.x) {
        const float* wr = w_ih0 + (size_t)j * EMB_;
        float s = b_ih0[j] + b_hh0[j];
        #pragma unroll 8
        for (int k = 0; k < EMB_; k++) s = fmaf(se[k], wr[k], s);
        g_E2[v * HID_ + j] = s;
    }
    int gt = blockIdx.x * blockDim.x + threadIdx.x;
    // zero parity-0 state buffers (exactly B_*HID_ = 32768 = gridDim*blockDim elems)
    for (int i = gt; i < B_ * HID_; i += gridDim.x * blockDim.x) {
        g_h0[0][i] = 0.0f;
        g_h1[0][i] = 0.0f;
    }
    if (gt < QG) { g_bar_count[gt] = 0; g_bar_phase[gt] = 0; }
}

// ---------------- batch-group barrier (PG CTAs per group) ----------------
__device__ __forceinline__ void group_barrier(int q, unsigned target)
{
    __threadfence();      // each thread releases its own global stores
    __syncthreads();
    if (threadIdx.x == 0) {
        unsigned old = atomicAdd(&g_bar_count[q], 1u);
        if (old == PG - 1) {
            g_bar_count[q] = 0;
            __threadfence();
            atomicExch((unsigned*)&g_bar_phase[q], target);
        } else {
            while (g_bar_phase[q] < target) { }
        }
    }
    __syncthreads();
}

// ---------------- persistent RNN kernel ----------------
__global__ void __launch_bounds__(RNN_THREADS, 1)
rnn_kernel(const int* __restrict__ xg,
           const float* __restrict__ w_hh0,
           const float* __restrict__ w_ih1,
           const float* __restrict__ b_ih1,
           const float* __restrict__ w_hh1,
           const float* __restrict__ b_hh1)
{
    extern __shared__ float smem[];
    float* ws0    = smem;                    // [CJ][WPAD]  w_hh0 slice
    float* ws1i   = ws0  + CJ * WPAD;        // [CJ][WPAD]  w_ih1 slice
    float* ws1h   = ws1i + CJ * WPAD;        // [CJ][WPAD]  w_hh1 slice
    float* h_a    = ws1h + CJ * WPAD;        // [BQ][WPAD]  staged h (h0_prev, then h0_cur)
    float* h_b    = h_a  + BQ * WPAD;        // [BQ][WPAD]  staged h1_prev
    float* e2s    = h_b  + BQ * WPAD;        // [VOCAB][CJ] E2 slice
    float* bias1s = e2s  + VOCAB_ * CJ;      // [CJ]

    const int tid  = threadIdx.x;
    const int q    = blockIdx.x >> 5;        // batch group 0..3
    const int p    = blockIdx.x & 31;        // column group 0..31
    const int j0   = p * CJ;
    const int b0   = q * BQ;
    const int warp = tid >> 5;
    const int lane = tid & 31;
    const int jl   = lane & 15;              // local column
    const int kh   = lane >> 4;              // k-half (0/1)
    const int bw   = warp * 4;               // local batch base for this warp

    // ---- load weight slices into SMEM (once) ----
    for (int idx = tid; idx < CJ * (HID_ / 4); idx += RNN_THREADS) {
        int r = idx >> 7;          // row 0..15
        int c = idx & 127;         // float4 index 0..127
        float4 a = *(const float4*)(w_hh0 + (size_t)(j0 + r) * HID_ + c * 4);
        *(float4*)(ws0 + r * WPAD + c * 4) = a;
        float4 bi = *(const float4*)(w_ih1 + (size_t)(j0 + r) * HID_ + c * 4);
        *(float4*)(ws1i + r * WPAD + c * 4) = bi;
        float4 bh = *(const float4*)(w_hh1 + (size_t)(j0 + r) * HID_ + c * 4);
        *(float4*)(ws1h + r * WPAD + c * 4) = bh;
    }
    for (int idx = tid; idx < VOCAB_ * CJ; idx += RNN_THREADS) {
        int v = idx >> 4;
        int j = idx & 15;
        e2s[idx] = g_E2[v * HID_ + j0 + j];
    }
    if (tid < CJ) bias1s[tid] = b_ih1[j0 + tid] + b_hh1[j0 + tid];
    __syncthreads();

    const float* w0row  = ws0  + jl * WPAD + kh * 256;
    const float* w1irow = ws1i + jl * WPAD + kh * 256;
    const float* w1hrow = ws1h + jl * WPAD + kh * 256;

    for (int t = 0; t < T_; t++) {
        const int cur = t & 1, nxt = cur ^ 1;

        // ---- stage h0_prev -> h_a, h1_prev -> h_b (via L2, skip L1) ----
        {
            const float* g0 = g_h0[cur] + (size_t)b0 * HID_;
            const float* g1 = g_h1[cur] + (size_t)b0 * HID_;
            for (int idx = tid; idx < BQ * (HID_ / 4); idx += RNN_THREADS) {
                int r = idx >> 7, c = idx & 127;
                float4 a = __ldcg((const float4*)(g0 + (size_t)r * HID_ + c * 4));
                *(float4*)(h_a + r * WPAD + c * 4) = a;
                float4 b = __ldcg((const float4*)(g1 + (size_t)r * HID_ + c * 4));
                *(float4*)(h_b + r * WPAD + c * 4) = b;
            }
        }
        __syncthreads();

        // ---- layer 0: acc[bi] = sum_k h0_prev[b][k] * w_hh0[j][k] (this lane's k-half) ----
        float acc[4] = {0.f, 0.f, 0.f, 0.f};
        {
            const float* hp0 = h_a + bw * WPAD + kh * 256;
            #pragma unroll 4
            for (int kc = 0; kc < 256; kc += 8) {
                float4 wA = *(const float4*)(w0row + kc);
                float4 wB = *(const float4*)(w0row + kc + 4);
                #pragma unroll
                for (int bi = 0; bi < 4; bi++) {
                    const float* hp = hp0 + bi * WPAD + kc;
                    float4 hA = *(const float4*)(hp);
                    float4 hB = *(const float4*)(hp + 4);
                    float a = acc[bi];
                    a = fmaf(hA.x, wA.x, a); a = fmaf(hA.y, wA.y, a);
                    a = fmaf(hA.z, wA.z, a); a = fmaf(hA.w, wA.w, a);
                    a = fmaf(hB.x, wB.x, a); a = fmaf(hB.y, wB.y, a);
                    a = fmaf(hB.z, wB.z, a); a = fmaf(hB.w, wB.w, a);
                    acc[bi] = a;
                }
            }
        }
        #pragma unroll
        for (int bi = 0; bi < 4; bi++)
            acc[bi] += __shfl_xor_sync(0xffffffffu, acc[bi], 16);

        if (kh == 0) {
            #pragma unroll
            for (int bi = 0; bi < 4; bi++) {
                int gb = b0 + bw + bi;
                int tok = xg[(size_t)gb * T_ + t];
                float val = acc[bi] + e2s[tok * CJ + jl];
                __stcg(g_h0[nxt] + (size_t)gb * HID_ + j0 + jl, tanhf(val));
            }
        }
        group_barrier(q, 2u * t + 1u);

        // ---- restage h0_cur (full 512 cols) -> h_a ----
        {
            const float* g0n = g_h0[nxt] + (size_t)b0 * HID_;
            for (int idx = tid; idx < BQ * (HID_ / 4); idx += RNN_THREADS) {
                int r = idx >> 7, c = idx & 127;
                float4 a = __ldcg((const float4*)(g0n + (size_t)r * HID_ + c * 4));
                *(float4*)(h_a + r * WPAD + c * 4) = a;
            }
        }
        __syncthreads();

        // ---- layer 1: sum_k h0_cur*w_ih1 + h1_prev*w_hh1 ----
        float acc2[4] = {0.f, 0.f, 0.f, 0.f};
        {
            const float* hp0 = h_a + bw * WPAD + kh * 256;
            const float* hq0 = h_b + bw * WPAD + kh * 256;
            #pragma unroll 2
            for (int kc = 0; kc < 256; kc += 8) {
                float4 wiA = *(const float4*)(w1irow + kc);
                float4 wiB = *(const float4*)(w1irow + kc + 4);
                float4 whA = *(const float4*)(w1hrow + kc);
                float4 whB = *(const float4*)(w1hrow + kc + 4);
                #pragma unroll
                for (int bi = 0; bi < 4; bi++) {
                    const float* hp = hp0 + bi * WPAD + kc;
                    const float* hq = hq0 + bi * WPAD + kc;
                    float4 xA = *(const float4*)(hp);
                    float4 xB = *(const float4*)(hp + 4);
                    float4 yA = *(const float4*)(hq);
                    float4 yB = *(const float4*)(hq + 4);
                    float a = acc2[bi];
                    a = fmaf(xA.x, wiA.x, a); a = fmaf(xA.y, wiA.y, a);
                    a = fmaf(xA.z, wiA.z, a); a = fmaf(xA.w, wiA.w, a);
                    a = fmaf(xB.x, wiB.x, a); a = fmaf(xB.y, wiB.y, a);
                    a = fmaf(xB.z, wiB.z, a); a = fmaf(xB.w, wiB.w, a);
                    a = fmaf(yA.x, whA.x, a); a = fmaf(yA.y, whA.y, a);
                    a = fmaf(yA.z, whA.z, a); a = fmaf(yA.w, whA.w, a);
                    a = fmaf(yB.x, whB.x, a); a = fmaf(yB.y, whB.y, a);
                    a = fmaf(yB.z, whB.z, a); a = fmaf(yB.w, whB.w, a);
                    acc2[bi] = a;
                }
            }
        }
        #pragma unroll
        for (int bi = 0; bi < 4; bi++)
            acc2[bi] += __shfl_xor_sync(0xffffffffu, acc2[bi], 16);

        if (kh == 0) {
            float bia = bias1s[jl];
            #pragma unroll
            for (int bi = 0; bi < 4; bi++) {
                int gb = b0 + bw + bi;
                float h = tanhf(acc2[bi] + bia);
                __stcg(g_h1[nxt] + (size_t)gb * HID_ + j0 + jl, h);
                g_hout[((size_t)gb * T_ + t) * HID_ + j0 + jl] = h;
            }
        }
        group_barrier(q, 2u * t + 2u);
    }
}

// ---------------- final FC: logits = g_hout @ fc_w^T + fc_b ----------------
#define FC_BM 64
#define FC_BN 64
#define FC_BK 32

__global__ void __launch_bounds__(256)
fc_kernel(const float* __restrict__ fc_w,
          const float* __restrict__ fc_b,
          float* __restrict__ out)
{
    __shared__ float As[FC_BK][FC_BM];
    __shared__ float Bs[FC_BK][FC_BN];

    const int tx = threadIdx.x & 15;     // output col quad
    const int ty = threadIdx.x >> 4;     // output row quad
    const size_t i0 = (size_t)blockIdx.x * FC_BM;
    const int v0 = blockIdx.y * FC_BN;

    const int lr = threadIdx.x >> 2;     // loader row 0..63
    const int lc = threadIdx.x & 3;      // loader float4 col 0..3

    const float* Abase = g_hout + i0 * HID_;
    const float* Bbase = fc_w + (size_t)v0 * HID_;

    float acc[4][4] = {};

    for (int k0 = 0; k0 < HID_; k0 += FC_BK) {
        float4 a0 = *(const float4*)(Abase + (size_t)lr * HID_ + k0 + lc * 4);
        float4 a1 = *(const float4*)(Abase + (size_t)lr * HID_ + k0 + 16 + lc * 4);
        float4 w0 = *(const float4*)(Bbase + (size_t)lr * HID_ + k0 + lc * 4);
        float4 w1 = *(const float4*)(Bbase + (size_t)lr * HID_ + k0 + 16 + lc * 4);
        __syncthreads();
        As[lc * 4 + 0][lr] = a0.x; As[lc * 4 + 1][lr] = a0.y;
        As[lc * 4 + 2][lr] = a0.z; As[lc * 4 + 3][lr] = a0.w;
        As[16 + lc * 4 + 0][lr] = a1.x; As[16 + lc * 4 + 1][lr] = a1.y;
        As[16 + lc * 4 + 2][lr] = a1.z; As[16 + lc * 4 + 3][lr] = a1.w;
        Bs[lc * 4 + 0][lr] = w0.x; Bs[lc * 4 + 1][lr] = w0.y;
        Bs[lc * 4 + 2][lr] = w0.z; Bs[lc * 4 + 3][lr] = w0.w;
        Bs[16 + lc * 4 + 0][lr] = w1.x; Bs[16 + lc * 4 + 1][lr] = w1.y;
        Bs[16 + lc * 4 + 2][lr] = w1.z; Bs[16 + lc * 4 + 3][lr] = w1.w;
        __syncthreads();
        #pragma unroll
        for (int k = 0; k < FC_BK; k++) {
            float4 av = *(const float4*)&As[k][ty * 4];
            float4 bv = *(const float4*)&Bs[k][tx * 4];
            acc[0][0] = fmaf(av.x, bv.x, acc[0][0]); acc[0][1] = fmaf(av.x, bv.y, acc[0][1]);
            acc[0][2] = fmaf(av.x, bv.z, acc[0][2]); acc[0][3] = fmaf(av.x, bv.w, acc[0][3]);
            acc[1][0] = fmaf(av.y, bv.x, acc[1][0]); acc[1][1] = fmaf(av.y, bv.y, acc[1][1]);
            acc[1][2] = fmaf(av.y, bv.z, acc[1][2]); acc[1][3] = fmaf(av.y, bv.w, acc[1][3]);
            acc[2][0] = fmaf(av.z, bv.x, acc[2][0]); acc[2][1] = fmaf(av.z, bv.y, acc[2][1]);
            acc[2][2] = fmaf(av.z, bv.z, acc[2][2]); acc[2][3] = fmaf(av.z, bv.w, acc[2][3]);
            acc[3][0] = fmaf(av.w, bv.x, acc[3][0]); acc[3][1] = fmaf(av.w, bv.y, acc[3][1]);
            acc[3][2] = fmaf(av.w, bv.z, acc[3][2]); acc[3][3] = fmaf(av.w, bv.w, acc[3][3]);
        }
    }

    float4 bb = *(const float4*)(fc_b + v0 + tx * 4);
    #pragma unroll
    for (int m = 0; m < 4; m++) {
        float4 r;
        r.x = acc[m][0] + bb.x;
        r.y = acc[m][1] + bb.y;
        r.z = acc[m][2] + bb.z;
        r.w = acc[m][3] + bb.w;
        *(float4*)(out + (i0 + ty * 4 + m) * VOCAB_ + v0 + tx * 4) = r;
    }
}

// ---------------- launch ----------------
extern "C" void kernel_launch(void* const* d_in, const int* in_sizes, int n_in,
                              void* d_out, int out_size)
{
    const int* x        = (const int*)d_in[0];
    const float* emb    = (const float*)d_in[1];
    const float* w_ih0  = (const float*)d_in[2];
    const float* b_ih0  = (const float*)d_in[3];
    const float* w_hh0  = (const float*)d_in[4];
    const float* b_hh0  = (const float*)d_in[5];
    const float* w_ih1  = (const float*)d_in[6];
    const float* b_ih1  = (const float*)d_in[7];
    const float* w_hh1  = (const float*)d_in[8];
    const float* b_hh1  = (const float*)d_in[9];
    const float* fc_w   = (const float*)d_in[10];
    const float* fc_b   = (const float*)d_in[11];
    float* out = (float*)d_out;

    const size_t smem_bytes =
        (size_t)(3 * CJ * WPAD + 2 * BQ * WPAD + VOCAB_ * CJ + CJ) * sizeof(float);
    cudaFuncSetAttribute(rnn_kernel, cudaFuncAttributeMaxDynamicSharedMemorySize,
                         (int)smem_bytes);

    prep_kernel<<<VOCAB_, 128>>>(emb, w_ih0, b_ih0, b_hh0);
    rnn_kernel<<<NCTA, RNN_THREADS, smem_bytes>>>(x, w_hh0, w_ih1, b_ih1, w_hh1, b_hh1);
    fc_kernel<<<dim3((B_ * T_) / FC_BM, VOCAB_ / FC_BN), 256>>>(fc_w, fc_b, out);
}

// round 4
// speedup vs baseline: 1.3973x; 1.3973x over previous
#include <cuda_runtime.h>
#include <math.h>
#include <stdint.h>

#define B_     64
#define T_     1024
#define VOCAB_ 256
#define EMB_   128
#define HID_   512

// RNN partition: 4 batch groups x 32 column groups = 128 persistent CTAs
#define QG  4
#define PG  32
#define BQ  16     // batches per CTA
#define CJ  16     // hidden columns per CTA
#define NCTA (QG*PG)
#define RNN_THREADS 128
#define WPAD 516   // padded row stride in floats (512+4); 516*4 % 16 == 0 (16B aligned rows)

typedef unsigned long long u64;

// packed 2-wide fp32 FMA (SASS FFMA2); acc/a/b each hold two floats
__device__ __forceinline__ void fma2(u64& acc, u64 a, u64 b) {
    asm("fma.rn.f32x2 %0, %1, %2, %0;" : "+l"(acc) : "l"(a), "l"(b));
}
__device__ __forceinline__ float hsum2(u64 v) {
    float2 f = *reinterpret_cast<float2*>(&v);
    return f.x + f.y;
}

// ---------------- device global scratch (no cudaMalloc allowed) ----------------
__device__ __align__(16) float g_E2[VOCAB_ * HID_];            // emb@w_ih0^T + b_ih0 + b_hh0
__device__ __align__(16) float g_h0[2][B_ * HID_];             // ping-pong layer0 state
__device__ __align__(16) float g_h1[2][B_ * HID_];             // ping-pong layer1 state
__device__ __align__(16) float g_hout[(size_t)B_ * T_ * HID_]; // all h1 outputs (128 MB)
__device__ unsigned g_bar_count[QG];
__device__ volatile unsigned g_bar_phase[QG];

// ---------------- prep: E2 table, zero initial state, reset barriers ----------------
__global__ void prep_kernel(const float* __restrict__ emb,
                            const float* __restrict__ w_ih0,
                            const float* __restrict__ b_ih0,
                            const float* __restrict__ b_hh0)
{
    int v = blockIdx.x;  // 0..255 vocab row
    __shared__ float se[EMB_];
    for (int k = threadIdx.x; k < EMB_; k += blockDim.x) se[k] = emb[v * EMB_ + k];
    __syncthreads();
    for (int j = threadIdx.x; j < HID_; j += blockDim.x) {
        const float* wr = w_ih0 + (size_t)j * EMB_;
        float s = b_ih0[j] + b_hh0[j];
        #pragma unroll 8
        for (int k = 0; k < EMB_; k++) s = fmaf(se[k], wr[k], s);
        g_E2[v * HID_ + j] = s;
    }
    int gt = blockIdx.x * blockDim.x + threadIdx.x;
    for (int i = gt; i < B_ * HID_; i += gridDim.x * blockDim.x) {
        g_h0[0][i] = 0.0f;
        g_h1[0][i] = 0.0f;
    }
    if (gt < QG) { g_bar_count[gt] = 0; g_bar_phase[gt] = 0; }
}

// ---------------- batch-group barrier (PG CTAs per group) ----------------
__device__ __forceinline__ void group_barrier(int q, unsigned target)
{
    __threadfence();      // release this CTA's global stores
    __syncthreads();
    if (threadIdx.x == 0) {
        unsigned old = atomicAdd(&g_bar_count[q], 1u);
        if (old == PG - 1) {
            g_bar_count[q] = 0;
            __threadfence();
            atomicExch((unsigned*)&g_bar_phase[q], target);
        } else {
            while (g_bar_phase[q] < target) { }
        }
    }
    __syncthreads();
}

// ---------------- persistent RNN kernel ----------------
__global__ void __launch_bounds__(RNN_THREADS, 1)
rnn_kernel(const int* __restrict__ xg,
           const float* __restrict__ w_hh0,
           const float* __restrict__ w_ih1,
           const float* __restrict__ b_ih1,
           const float* __restrict__ w_hh1,
           const float* __restrict__ b_hh1)
{
    extern __shared__ float smem[];
    float* ws0    = smem;                    // [CJ][WPAD]  w_hh0 slice
    float* ws1i   = ws0  + CJ * WPAD;        // [CJ][WPAD]  w_ih1 slice
    float* ws1h   = ws1i + CJ * WPAD;        // [CJ][WPAD]  w_hh1 slice
    float* h_a    = ws1h + CJ * WPAD;        // [BQ][WPAD]  staged h0 (prev, then cur)
    float* h_b    = h_a  + BQ * WPAD;        // [BQ][WPAD]  staged h1_prev
    float* e2s    = h_b  + BQ * WPAD;        // [VOCAB][CJ] E2 slice
    float* bias1s = e2s  + VOCAB_ * CJ;      // [CJ]

    const int tid  = threadIdx.x;
    const int q    = blockIdx.x >> 5;        // batch group 0..3
    const int p    = blockIdx.x & 31;        // column group 0..31
    const int j0   = p * CJ;
    const int b0   = q * BQ;
    const int warp = tid >> 5;
    const int lane = tid & 31;
    const int jl   = lane & 15;              // local column
    const int kh   = lane >> 4;              // k-half (0/1), 256 k each
    const int bw   = warp * 4;               // local batch base for this warp

    // ---- load weight slices + E2 slice into SMEM (once) ----
    for (int idx = tid; idx < CJ * (HID_ / 4); idx += RNN_THREADS) {
        int r = idx >> 7;          // row 0..15
        int c = idx & 127;         // float4 index 0..127
        float4 a = *(const float4*)(w_hh0 + (size_t)(j0 + r) * HID_ + c * 4);
        *(float4*)(ws0 + r * WPAD + c * 4) = a;
        float4 bi = *(const float4*)(w_ih1 + (size_t)(j0 + r) * HID_ + c * 4);
        *(float4*)(ws1i + r * WPAD + c * 4) = bi;
        float4 bh = *(const float4*)(w_hh1 + (size_t)(j0 + r) * HID_ + c * 4);
        *(float4*)(ws1h + r * WPAD + c * 4) = bh;
    }
    for (int idx = tid; idx < VOCAB_ * CJ; idx += RNN_THREADS) {
        int v = idx >> 4;
        int j = idx & 15;
        e2s[idx] = g_E2[v * HID_ + j0 + j];
    }
    if (tid < CJ) bias1s[tid] = b_ih1[j0 + tid] + b_hh1[j0 + tid];

    // ---- pre-loop: stage h0_{-1} = zeros from g_h0[0] ----
    for (int idx = tid; idx < BQ * (HID_ / 4); idx += RNN_THREADS) {
        int r = idx >> 7, c = idx & 127;
        float4 a = __ldcg((const float4*)(g_h0[0] + (size_t)(b0 + r) * HID_ + c * 4));
        *(float4*)(h_a + r * WPAD + c * 4) = a;
    }
    __syncthreads();

    const u64* w0row  = (const u64*)(ws0  + jl * WPAD + kh * 256);
    const u64* w1irow = (const u64*)(ws1i + jl * WPAD + kh * 256);
    const u64* w1hrow = (const u64*)(ws1h + jl * WPAD + kh * 256);

    for (int t = 0; t < T_; t++) {
        const int wbuf = (t & 1) ^ 1;        // buffer written this step (h0 and h1)
        const int h1prev = t & 1;            // buffer holding h1_{t-1}

        // prefetch tokens for this step (used in layer0 epilogue)
        int tok[4];
        #pragma unroll
        for (int bi = 0; bi < 4; bi++)
            tok[bi] = __ldg(xg + (size_t)(b0 + bw + bi) * T_ + t);

        // ---- layer 0: acc[bi] = sum_k h0_prev[b][k] * w_hh0[j][k] (this lane's k-half) ----
        u64 acc[4] = {0ULL, 0ULL, 0ULL, 0ULL};
        {
            const float* hp0 = h_a + bw * WPAD + kh * 256;
            #pragma unroll 4
            for (int kc = 0; kc < 32; kc++) {          // 8 floats (4 u64) per iter
                ulonglong2 wA = ((const ulonglong2*)w0row)[2 * kc];
                ulonglong2 wB = ((const ulonglong2*)w0row)[2 * kc + 1];
                #pragma unroll
                for (int bi = 0; bi < 4; bi++) {
                    const ulonglong2* hp = (const ulonglong2*)(hp0 + bi * WPAD);
                    ulonglong2 hA = hp[2 * kc];
                    ulonglong2 hB = hp[2 * kc + 1];
                    fma2(acc[bi], hA.x, wA.x);
                    fma2(acc[bi], hA.y, wA.y);
                    fma2(acc[bi], hB.x, wB.x);
                    fma2(acc[bi], hB.y, wB.y);
                }
            }
        }
        float accs[4];
        #pragma unroll
        for (int bi = 0; bi < 4; bi++) {
            accs[bi] = hsum2(acc[bi]);
            accs[bi] += __shfl_xor_sync(0xffffffffu, accs[bi], 16);
        }
        if (kh == 0) {
            #pragma unroll
            for (int bi = 0; bi < 4; bi++) {
                int gb = b0 + bw + bi;
                float val = accs[bi] + e2s[tok[bi] * CJ + jl];
                __stcg(g_h0[wbuf] + (size_t)gb * HID_ + j0 + jl, tanhf(val));
            }
        }

        // ---- single barrier per step: publishes h0_t and (from t-1) h1_{t-1} ----
        group_barrier(q, (unsigned)(t + 1));

        // ---- stage h_a <- h0_t (full), h_b <- h1_{t-1} (full) ----
        {
            const float* g0 = g_h0[wbuf]   + (size_t)b0 * HID_;
            const float* g1 = g_h1[h1prev] + (size_t)b0 * HID_;
            for (int idx = tid; idx < BQ * (HID_ / 4); idx += RNN_THREADS) {
                int r = idx >> 7, c = idx & 127;
                float4 a = __ldcg((const float4*)(g0 + (size_t)r * HID_ + c * 4));
                *(float4*)(h_a + r * WPAD + c * 4) = a;
                float4 b = __ldcg((const float4*)(g1 + (size_t)r * HID_ + c * 4));
                *(float4*)(h_b + r * WPAD + c * 4) = b;
            }
        }
        __syncthreads();

        // ---- layer 1: sum_k h0_t*w_ih1 + h1_{t-1}*w_hh1 ----
        u64 acc2[4] = {0ULL, 0ULL, 0ULL, 0ULL};
        {
            const float* hp0 = h_a + bw * WPAD + kh * 256;
            const float* hq0 = h_b + bw * WPAD + kh * 256;
            #pragma unroll 2
            for (int kc = 0; kc < 32; kc++) {
                ulonglong2 wiA = ((const ulonglong2*)w1irow)[2 * kc];
                ulonglong2 wiB = ((const ulonglong2*)w1irow)[2 * kc + 1];
                ulonglong2 whA = ((const ulonglong2*)w1hrow)[2 * kc];
                ulonglong2 whB = ((const ulonglong2*)w1hrow)[2 * kc + 1];
                #pragma unroll
                for (int bi = 0; bi < 4; bi++) {
                    const ulonglong2* hp = (const ulonglong2*)(hp0 + bi * WPAD);
                    const ulonglong2* hq = (const ulonglong2*)(hq0 + bi * WPAD);
                    ulonglong2 xA = hp[2 * kc];
                    ulonglong2 xB = hp[2 * kc + 1];
                    ulonglong2 yA = hq[2 * kc];
                    ulonglong2 yB = hq[2 * kc + 1];
                    fma2(acc2[bi], xA.x, wiA.x);
                    fma2(acc2[bi], xA.y, wiA.y);
                    fma2(acc2[bi], xB.x, wiB.x);
                    fma2(acc2[bi], xB.y, wiB.y);
                    fma2(acc2[bi], yA.x, whA.x);
                    fma2(acc2[bi], yA.y, whA.y);
                    fma2(acc2[bi], yB.x, whB.x);
                    fma2(acc2[bi], yB.y, whB.y);
                }
            }
        }
        float acc2s[4];
        #pragma unroll
        for (int bi = 0; bi < 4; bi++) {
            acc2s[bi] = hsum2(acc2[bi]);
            acc2s[bi] += __shfl_xor_sync(0xffffffffu, acc2s[bi], 16);
        }
        if (kh == 0) {
            float bia = bias1s[jl];
            #pragma unroll
            for (int bi = 0; bi < 4; bi++) {
                int gb = b0 + bw + bi;
                float h = tanhf(acc2s[bi] + bia);
                __stcg(g_h1[wbuf] + (size_t)gb * HID_ + j0 + jl, h);
                g_hout[((size_t)gb * T_ + t) * HID_ + j0 + jl] = h;
            }
        }
        // no second barrier: next step's barrier orders these h1 writes,
        // and buffer reuse is provably after the consumer's next arrival
    }
}

// ---------------- final FC: logits = g_hout @ fc_w^T + fc_b ----------------
#define FC_BM 64
#define FC_BN 64
#define FC_BK 32

__global__ void __launch_bounds__(256)
fc_kernel(const float* __restrict__ fc_w,
          const float* __restrict__ fc_b,
          float* __restrict__ out)
{
    __shared__ float As[FC_BK][FC_BM];
    __shared__ float Bs[FC_BK][FC_BN];

    const int tx = threadIdx.x & 15;     // output col quad
    const int ty = threadIdx.x >> 4;     // output row quad
    const size_t i0 = (size_t)blockIdx.x * FC_BM;
    const int v0 = blockIdx.y * FC_BN;

    const int lr = threadIdx.x >> 2;     // loader row 0..63
    const int lc = threadIdx.x & 3;      // loader float4 col 0..3

    const float* Abase = g_hout + i0 * HID_;
    const float* Bbase = fc_w + (size_t)v0 * HID_;

    float acc[4][4] = {};

    for (int k0 = 0; k0 < HID_; k0 += FC_BK) {
        float4 a0 = *(const float4*)(Abase + (size_t)lr * HID_ + k0 + lc * 4);
        float4 a1 = *(const float4*)(Abase + (size_t)lr * HID_ + k0 + 16 + lc * 4);
        float4 w0 = *(const float4*)(Bbase + (size_t)lr * HID_ + k0 + lc * 4);
        float4 w1 = *(const float4*)(Bbase + (size_t)lr * HID_ + k0 + 16 + lc * 4);
        __syncthreads();
        As[lc * 4 + 0][lr] = a0.x; As[lc * 4 + 1][lr] = a0.y;
        As[lc * 4 + 2][lr] = a0.z; As[lc * 4 + 3][lr] = a0.w;
        As[16 + lc * 4 + 0][lr] = a1.x; As[16 + lc * 4 + 1][lr] = a1.y;
        As[16 + lc * 4 + 2][lr] = a1.z; As[16 + lc * 4 + 3][lr] = a1.w;
        Bs[lc * 4 + 0][lr] = w0.x; Bs[lc * 4 + 1][lr] = w0.y;
        Bs[lc * 4 + 2][lr] = w0.z; Bs[lc * 4 + 3][lr] = w0.w;
        Bs[16 + lc * 4 + 0][lr] = w1.x; Bs[16 + lc * 4 + 1][lr] = w1.y;
        Bs[16 + lc * 4 + 2][lr] = w1.z; Bs[16 + lc * 4 + 3][lr] = w1.w;
        __syncthreads();
        #pragma unroll
        for (int k = 0; k < FC_BK; k++) {
            float4 av = *(const float4*)&As[k][ty * 4];
            float4 bv = *(const float4*)&Bs[k][tx * 4];
            acc[0][0] = fmaf(av.x, bv.x, acc[0][0]); acc[0][1] = fmaf(av.x, bv.y, acc[0][1]);
            acc[0][2] = fmaf(av.x, bv.z, acc[0][2]); acc[0][3] = fmaf(av.x, bv.w, acc[0][3]);
            acc[1][0] = fmaf(av.y, bv.x, acc[1][0]); acc[1][1] = fmaf(av.y, bv.y, acc[1][1]);
            acc[1][2] = fmaf(av.y, bv.z, acc[1][2]); acc[1][3] = fmaf(av.y, bv.w, acc[1][3]);
            acc[2][0] = fmaf(av.z, bv.x, acc[2][0]); acc[2][1] = fmaf(av.z, bv.y, acc[2][1]);
            acc[2][2] = fmaf(av.z, bv.z, acc[2][2]); acc[2][3] = fmaf(av.z, bv.w, acc[2][3]);
            acc[3][0] = fmaf(av.w, bv.x, acc[3][0]); acc[3][1] = fmaf(av.w, bv.y, acc[3][1]);
            acc[3][2] = fmaf(av.w, bv.z, acc[3][2]); acc[3][3] = fmaf(av.w, bv.w, acc[3][3]);
        }
    }

    float4 bb = *(const float4*)(fc_b + v0 + tx * 4);
    #pragma unroll
    for (int m = 0; m < 4; m++) {
        float4 r;
        r.x = acc[m][0] + bb.x;
        r.y = acc[m][1] + bb.y;
        r.z = acc[m][2] + bb.z;
        r.w = acc[m][3] + bb.w;
        *(float4*)(out + (i0 + ty * 4 + m) * VOCAB_ + v0 + tx * 4) = r;
    }
}

// ---------------- launch ----------------
extern "C" void kernel_launch(void* const* d_in, const int* in_sizes, int n_in,
                              void* d_out, int out_size)
{
    const int* x        = (const int*)d_in[0];
    const float* emb    = (const float*)d_in[1];
    const float* w_ih0  = (const float*)d_in[2];
    const float* b_ih0  = (const float*)d_in[3];
    const float* w_hh0  = (const float*)d_in[4];
    const float* b_hh0  = (const float*)d_in[5];
    const float* w_ih1  = (const float*)d_in[6];
    const float* b_ih1  = (const float*)d_in[7];
    const float* w_hh1  = (const float*)d_in[8];
    const float* b_hh1  = (const float*)d_in[9];
    const float* fc_w   = (const float*)d_in[10];
    const float* fc_b   = (const float*)d_in[11];
    float* out = (float*)d_out;

    const size_t smem_bytes =
        (size_t)(3 * CJ * WPAD + 2 * BQ * WPAD + VOCAB_ * CJ + CJ) * sizeof(float);
    cudaFuncSetAttribute(rnn_kernel, cudaFuncAttributeMaxDynamicSharedMemorySize,
                         (int)smem_bytes);

    prep_kernel<<<VOCAB_, 128>>>(emb, w_ih0, b_ih0, b_hh0);
    rnn_kernel<<<NCTA, RNN_THREADS, smem_bytes>>>(x, w_hh0, w_ih1, b_ih1, w_hh1, b_hh1);
    fc_kernel<<<dim3((B_ * T_) / FC_BM, VOCAB_ / FC_BN), 256>>>(fc_w, fc_b, out);
}